// round 5
// baseline (speedup 1.0000x reference)
#include <cuda_runtime.h>

#define D 256

// Scratch: per-node attention scalars (N = 50000, padded)
__device__ float g_al[65536];
__device__ float g_ar[65536];

// Kernel 1: per-node dots a_l = node.att_l, a_r = node.att_r, and out = 0.1*node_0
// One warp per node; 8 nodes per 256-thread block.
__global__ void node_pre_kernel(const float* __restrict__ node,
                                const float* __restrict__ node0,
                                const float* __restrict__ att_l,
                                const float* __restrict__ att_r,
                                float* __restrict__ out, int N) {
    __shared__ float s_l[D];
    __shared__ float s_r[D];
    int tid = threadIdx.x;
    s_l[tid] = att_l[tid];
    s_r[tid] = att_r[tid];
    __syncthreads();

    int warp = tid >> 5;
    int lane = tid & 31;
    int n = blockIdx.x * 8 + warp;
    if (n >= N) return;

    const float4* row  = (const float4*)(node  + (size_t)n * D);
    const float4* row0 = (const float4*)(node0 + (size_t)n * D);
    float4*       orow = (float4*)(out + (size_t)n * D);
    const float4* sl4 = (const float4*)s_l;
    const float4* sr4 = (const float4*)s_r;

    float sl = 0.f, sr = 0.f;
#pragma unroll
    for (int i = 0; i < 2; i++) {
        int idx = lane + 32 * i;
        float4 v  = row[idx];
        float4 al = sl4[idx];
        float4 ar = sr4[idx];
        sl += v.x * al.x + v.y * al.y + v.z * al.z + v.w * al.w;
        sr += v.x * ar.x + v.y * ar.y + v.z * ar.z + v.w * ar.w;
        float4 v0 = row0[idx];
        orow[idx] = make_float4(0.1f * v0.x, 0.1f * v0.y, 0.1f * v0.z, 0.1f * v0.w);
    }
#pragma unroll
    for (int o = 16; o > 0; o >>= 1) {
        sl += __shfl_xor_sync(0xffffffffu, sl, o);
        sr += __shfl_xor_sync(0xffffffffu, sr, o);
    }
    if (lane == 0) {
        g_al[n] = sl;
        g_ar[n] = sr;
    }
}

// Kernel 2: edge scatter. One warp per edge. coef = tanh(a_l[src]+a_r[dst]) * w_e,
// out[dst] += node[src] * coef via vector reductions (red.global.add.v4.f32).
// NOTE: edge_index is int32 (JAX x64 disabled -> jnp.int64 materializes as int32).
__global__ void edge_scatter_kernel(const float* __restrict__ node,
                                    const int* __restrict__ ei,
                                    const float* __restrict__ ew,
                                    float* __restrict__ out, int E) {
    int gwarp = (blockIdx.x * blockDim.x + threadIdx.x) >> 5;
    int lane = threadIdx.x & 31;
    if (gwarp >= E) return;

    int s = __ldg(ei + gwarp);        // src (row 0 of edge_index)
    int d = __ldg(ei + gwarp + E);    // dst (row 1)
    float coef = tanhf(g_al[s] + g_ar[d]) * __ldg(ew + gwarp);

    const float4* src = (const float4*)(node + (size_t)s * D);
    float4*       dst = (float4*)(out + (size_t)d * D);
#pragma unroll
    for (int i = 0; i < 2; i++) {
        int idx = lane + 32 * i;
        float4 v = src[idx];
        float a = v.x * coef, b = v.y * coef, c = v.z * coef, e = v.w * coef;
        asm volatile("red.global.add.v4.f32 [%0], {%1, %2, %3, %4};"
                     :: "l"(dst + idx), "f"(a), "f"(b), "f"(c), "f"(e)
                     : "memory");
    }
}

// Kernel 3: in-place LayerNorm over D + ReLU. One warp per node.
__global__ void ln_relu_kernel(float* __restrict__ out,
                               const float* __restrict__ w,
                               const float* __restrict__ b, int N) {
    int gwarp = (blockIdx.x * blockDim.x + threadIdx.x) >> 5;
    int lane = threadIdx.x & 31;
    if (gwarp >= N) return;

    float4* row = (float4*)(out + (size_t)gwarp * D);
    float4 v0 = row[lane];
    float4 v1 = row[lane + 32];

    float sum = v0.x + v0.y + v0.z + v0.w + v1.x + v1.y + v1.z + v1.w;
    float sq  = v0.x * v0.x + v0.y * v0.y + v0.z * v0.z + v0.w * v0.w
              + v1.x * v1.x + v1.y * v1.y + v1.z * v1.z + v1.w * v1.w;
#pragma unroll
    for (int o = 16; o > 0; o >>= 1) {
        sum += __shfl_xor_sync(0xffffffffu, sum, o);
        sq  += __shfl_xor_sync(0xffffffffu, sq, o);
    }
    float mean = sum * (1.0f / D);
    float var  = sq * (1.0f / D) - mean * mean;
    float inv  = rsqrtf(var + 1e-5f);

    const float4* w4 = (const float4*)w;
    const float4* b4 = (const float4*)b;
#pragma unroll
    for (int i = 0; i < 2; i++) {
        int idx = lane + 32 * i;
        float4 v = (i == 0) ? v0 : v1;
        float4 ww = __ldg(w4 + idx);
        float4 bb = __ldg(b4 + idx);
        float4 r;
        r.x = fmaxf((v.x - mean) * inv * ww.x + bb.x, 0.0f);
        r.y = fmaxf((v.y - mean) * inv * ww.y + bb.y, 0.0f);
        r.z = fmaxf((v.z - mean) * inv * ww.z + bb.z, 0.0f);
        r.w = fmaxf((v.w - mean) * inv * ww.w + bb.w, 0.0f);
        row[idx] = r;
    }
}

extern "C" void kernel_launch(void* const* d_in, const int* in_sizes, int n_in,
                              void* d_out, int out_size) {
    const float* node  = (const float*)d_in[0];
    const float* node0 = (const float*)d_in[1];
    const int*   ei    = (const int*)d_in[2];
    const float* ew    = (const float*)d_in[3];
    // d_in[4] = batch_ptr (unused in node-mode LayerNorm)
    const float* att_l = (const float*)d_in[5];
    const float* att_r = (const float*)d_in[6];
    const float* lnw   = (const float*)d_in[7];
    const float* lnb   = (const float*)d_in[8];
    float* out = (float*)d_out;

    int N = in_sizes[0] / D;
    int E = in_sizes[3];

    // 1) per-node dots + out = 0.1 * node_0
    node_pre_kernel<<<(N + 7) / 8, 256>>>(node, node0, att_l, att_r, out, N);
    // 2) edge scatter: one warp per edge, 8 edges per block
    edge_scatter_kernel<<<(E + 7) / 8, 256>>>(node, ei, ew, out, E);
    // 3) LayerNorm + ReLU in place
    ln_relu_kernel<<<(N + 7) / 8, 256>>>(out, lnw, lnb, N);
}

// round 6
// speedup vs baseline: 1.0538x; 1.0538x over previous
#include <cuda_runtime.h>

#define D 256
#define NMAX 65536
#define EMAX 1048576

// Scratch (static __device__ — no allocations allowed)
__device__ float g_al[NMAX];
__device__ float g_ar[NMAX];
__device__ int   g_cnt[NMAX];
__device__ int   g_off[NMAX + 1];
__device__ int   g_pos[NMAX];
__device__ int   g_src[EMAX];
__device__ float g_coef[EMAX];

// K1: per-node dots a_l, a_r (warp per node) + zero counters
__global__ void node_pre_kernel(const float* __restrict__ node,
                                const float* __restrict__ att_l,
                                const float* __restrict__ att_r, int N) {
    __shared__ float s_l[D];
    __shared__ float s_r[D];
    int tid = threadIdx.x;
    s_l[tid] = att_l[tid];
    s_r[tid] = att_r[tid];
    __syncthreads();

    int warp = tid >> 5, lane = tid & 31;
    int n = blockIdx.x * 8 + warp;
    if (n >= N) return;

    const float4* row = (const float4*)(node + (size_t)n * D);
    const float4* sl4 = (const float4*)s_l;
    const float4* sr4 = (const float4*)s_r;

    float sl = 0.f, sr = 0.f;
#pragma unroll
    for (int i = 0; i < 2; i++) {
        int idx = lane + 32 * i;
        float4 v = row[idx];
        float4 al = sl4[idx];
        float4 ar = sr4[idx];
        sl += v.x * al.x + v.y * al.y + v.z * al.z + v.w * al.w;
        sr += v.x * ar.x + v.y * ar.y + v.z * ar.z + v.w * ar.w;
    }
#pragma unroll
    for (int o = 16; o > 0; o >>= 1) {
        sl += __shfl_xor_sync(0xffffffffu, sl, o);
        sr += __shfl_xor_sync(0xffffffffu, sr, o);
    }
    if (lane == 0) {
        g_al[n] = sl;
        g_ar[n] = sr;
        g_cnt[n] = 0;
    }
}

// K2: in-degree histogram
__global__ void hist_kernel(const int* __restrict__ ei, int E) {
    int i = blockIdx.x * blockDim.x + threadIdx.x;
    if (i < E) atomicAdd(&g_cnt[__ldg(ei + E + i)], 1);
}

// K3: exclusive scan of g_cnt -> g_off (and g_pos). Single block, 1024 threads.
__global__ void scan_kernel(int N, int E) {
    __shared__ int ssum[1024];
    int t = threadIdx.x;
    int chunk = (N + 1023) / 1024;
    int base = t * chunk;
    int s = 0;
    for (int i = 0; i < chunk; i++) {
        int idx = base + i;
        if (idx < N) s += g_cnt[idx];
    }
    ssum[t] = s;
    __syncthreads();
    for (int o = 1; o < 1024; o <<= 1) {
        int v = 0;
        if (t >= o) v = ssum[t - o];
        __syncthreads();
        if (t >= o) ssum[t] += v;
        __syncthreads();
    }
    int run = (t == 0) ? 0 : ssum[t - 1];
    for (int i = 0; i < chunk; i++) {
        int idx = base + i;
        if (idx < N) {
            g_off[idx] = run;
            g_pos[idx] = run;
            run += g_cnt[idx];
        }
    }
    if (t == 0) g_off[N] = E;
}

// K4: scatter edges into CSR slots; compute coef once here (permuted storage
// so the aggregation kernel reads src/coef contiguously per segment).
__global__ void scatter_kernel(const int* __restrict__ ei,
                               const float* __restrict__ ew, int E) {
    int i = blockIdx.x * blockDim.x + threadIdx.x;
    if (i >= E) return;
    int s = __ldg(ei + i);
    int d = __ldg(ei + E + i);
    float coef = tanhf(g_al[s] + g_ar[d]) * __ldg(ew + i);
    int p = atomicAdd(&g_pos[d], 1);
    g_src[p] = s;
    g_coef[p] = coef;
}

// K5: warp-per-dst gather + register accumulation + fused 0.1*node_0 +
// LayerNorm + ReLU epilogue. Single store per output row.
__global__ void agg_ln_kernel(const float* __restrict__ node,
                              const float* __restrict__ node0,
                              const float* __restrict__ w,
                              const float* __restrict__ b,
                              float* __restrict__ out, int N) {
    int warp = threadIdx.x >> 5, lane = threadIdx.x & 31;
    int n = blockIdx.x * 8 + warp;
    if (n >= N) return;

    int k0 = __ldg(&g_off[n]);
    int k1 = __ldg(&g_off[n + 1]);

    float4 a0 = make_float4(0.f, 0.f, 0.f, 0.f);
    float4 a1 = make_float4(0.f, 0.f, 0.f, 0.f);

    int e = k0;
    // 2-deep software pipeline on the row loads to expose MLP
    for (; e + 1 < k1; e += 2) {
        int s0 = __ldg(g_src + e);
        int s1 = __ldg(g_src + e + 1);
        float c0 = __ldg(g_coef + e);
        float c1 = __ldg(g_coef + e + 1);
        const float4* r0 = (const float4*)(node + (size_t)s0 * D);
        const float4* r1 = (const float4*)(node + (size_t)s1 * D);
        float4 v0 = __ldg(r0 + lane),       u0 = __ldg(r0 + lane + 32);
        float4 v1 = __ldg(r1 + lane),       u1 = __ldg(r1 + lane + 32);
        a0.x += v0.x * c0; a0.y += v0.y * c0; a0.z += v0.z * c0; a0.w += v0.w * c0;
        a1.x += u0.x * c0; a1.y += u0.y * c0; a1.z += u0.z * c0; a1.w += u0.w * c0;
        a0.x += v1.x * c1; a0.y += v1.y * c1; a0.z += v1.z * c1; a0.w += v1.w * c1;
        a1.x += u1.x * c1; a1.y += u1.y * c1; a1.z += u1.z * c1; a1.w += u1.w * c1;
    }
    if (e < k1) {
        int s0 = __ldg(g_src + e);
        float c0 = __ldg(g_coef + e);
        const float4* r0 = (const float4*)(node + (size_t)s0 * D);
        float4 v0 = __ldg(r0 + lane), u0 = __ldg(r0 + lane + 32);
        a0.x += v0.x * c0; a0.y += v0.y * c0; a0.z += v0.z * c0; a0.w += v0.w * c0;
        a1.x += u0.x * c0; a1.y += u0.y * c0; a1.z += u0.z * c0; a1.w += u0.w * c0;
    }

    // + 0.1 * node_0
    const float4* row0 = (const float4*)(node0 + (size_t)n * D);
    float4 z0 = __ldg(row0 + lane), z1 = __ldg(row0 + lane + 32);
    a0.x += 0.1f * z0.x; a0.y += 0.1f * z0.y; a0.z += 0.1f * z0.z; a0.w += 0.1f * z0.w;
    a1.x += 0.1f * z1.x; a1.y += 0.1f * z1.y; a1.z += 0.1f * z1.z; a1.w += 0.1f * z1.w;

    // LayerNorm over D=256 + ReLU
    float sum = a0.x + a0.y + a0.z + a0.w + a1.x + a1.y + a1.z + a1.w;
    float sq  = a0.x * a0.x + a0.y * a0.y + a0.z * a0.z + a0.w * a0.w
              + a1.x * a1.x + a1.y * a1.y + a1.z * a1.z + a1.w * a1.w;
#pragma unroll
    for (int o = 16; o > 0; o >>= 1) {
        sum += __shfl_xor_sync(0xffffffffu, sum, o);
        sq  += __shfl_xor_sync(0xffffffffu, sq, o);
    }
    float mean = sum * (1.0f / D);
    float var  = sq * (1.0f / D) - mean * mean;
    float inv  = rsqrtf(var + 1e-5f);

    const float4* w4 = (const float4*)w;
    const float4* b4 = (const float4*)b;
    float4* orow = (float4*)(out + (size_t)n * D);
#pragma unroll
    for (int i = 0; i < 2; i++) {
        int idx = lane + 32 * i;
        float4 v = (i == 0) ? a0 : a1;
        float4 ww = __ldg(w4 + idx);
        float4 bb = __ldg(b4 + idx);
        float4 r;
        r.x = fmaxf((v.x - mean) * inv * ww.x + bb.x, 0.0f);
        r.y = fmaxf((v.y - mean) * inv * ww.y + bb.y, 0.0f);
        r.z = fmaxf((v.z - mean) * inv * ww.z + bb.z, 0.0f);
        r.w = fmaxf((v.w - mean) * inv * ww.w + bb.w, 0.0f);
        orow[idx] = r;
    }
}

extern "C" void kernel_launch(void* const* d_in, const int* in_sizes, int n_in,
                              void* d_out, int out_size) {
    const float* node  = (const float*)d_in[0];
    const float* node0 = (const float*)d_in[1];
    const int*   ei    = (const int*)d_in[2];
    const float* ew    = (const float*)d_in[3];
    // d_in[4] = batch_ptr (unused in node-mode LayerNorm)
    const float* att_l = (const float*)d_in[5];
    const float* att_r = (const float*)d_in[6];
    const float* lnw   = (const float*)d_in[7];
    const float* lnb   = (const float*)d_in[8];
    float* out = (float*)d_out;

    int N = in_sizes[0] / D;
    int E = in_sizes[3];

    node_pre_kernel<<<(N + 7) / 8, 256>>>(node, att_l, att_r, N);
    hist_kernel<<<(E + 255) / 256, 256>>>(ei, E);
    scan_kernel<<<1, 1024>>>(N, E);
    scatter_kernel<<<(E + 255) / 256, 256>>>(ei, ew, E);
    agg_ln_kernel<<<(N + 7) / 8, 256>>>(node, node0, lnw, lnb, out, N);
}

// round 9
// speedup vs baseline: 1.0622x; 1.0080x over previous
#include <cuda_runtime.h>

#define D 256
#define NMAX 65536
#define EMAX 1048576

// Scratch (static __device__ — no allocations allowed)
__device__ float g_al[NMAX];
__device__ float g_ar[NMAX];
__device__ int   g_cnt[NMAX];
__device__ int   g_off[NMAX + 1];
__device__ int   g_pos[NMAX];
__device__ int2  g_edge[EMAX];   // .x = src, .y = coef bits (packed 8B store)

// K1: per-node dots a_l, a_r (warp per node) + zero counters
__global__ void node_pre_kernel(const float* __restrict__ node,
                                const float* __restrict__ att_l,
                                const float* __restrict__ att_r, int N) {
    __shared__ float s_l[D];
    __shared__ float s_r[D];
    int tid = threadIdx.x;
    s_l[tid] = att_l[tid];
    s_r[tid] = att_r[tid];
    __syncthreads();

    int warp = tid >> 5, lane = tid & 31;
    int n = blockIdx.x * 8 + warp;
    if (n >= N) return;

    const float4* row = (const float4*)(node + (size_t)n * D);
    const float4* sl4 = (const float4*)s_l;
    const float4* sr4 = (const float4*)s_r;

    float sl = 0.f, sr = 0.f;
#pragma unroll
    for (int i = 0; i < 2; i++) {
        int idx = lane + 32 * i;
        float4 v = row[idx];
        float4 al = sl4[idx];
        float4 ar = sr4[idx];
        sl += v.x * al.x + v.y * al.y + v.z * al.z + v.w * al.w;
        sr += v.x * ar.x + v.y * ar.y + v.z * ar.z + v.w * ar.w;
    }
#pragma unroll
    for (int o = 16; o > 0; o >>= 1) {
        sl += __shfl_xor_sync(0xffffffffu, sl, o);
        sr += __shfl_xor_sync(0xffffffffu, sr, o);
    }
    if (lane == 0) {
        g_al[n] = sl;
        g_ar[n] = sr;
        g_cnt[n] = 0;
    }
}

// K2: in-degree histogram (vectorized index reads; E assumed %4==0 path + tail)
__global__ void hist_kernel(const int* __restrict__ ei, int E) {
    int i = blockIdx.x * blockDim.x + threadIdx.x;
    int nv = E >> 2;
    if (i < nv) {
        int4 d4 = __ldg((const int4*)(ei + E) + i);
        atomicAdd(&g_cnt[d4.x], 1);
        atomicAdd(&g_cnt[d4.y], 1);
        atomicAdd(&g_cnt[d4.z], 1);
        atomicAdd(&g_cnt[d4.w], 1);
    }
    int tail = nv * 4 + i;
    if (i < (E & 3)) {
        // handled by first (E&3) threads of the grid
        atomicAdd(&g_cnt[__ldg(ei + E + nv * 4 + i)], 1);
    }
    (void)tail;
}

// K3: exclusive scan of g_cnt -> g_off (and g_pos). Single block, 1024 threads.
__global__ void scan_kernel(int N, int E) {
    __shared__ int ssum[1024];
    int t = threadIdx.x;
    int chunk = (N + 1023) / 1024;
    int base = t * chunk;
    int s = 0;
    for (int i = 0; i < chunk; i++) {
        int idx = base + i;
        if (idx < N) s += g_cnt[idx];
    }
    ssum[t] = s;
    __syncthreads();
    for (int o = 1; o < 1024; o <<= 1) {
        int v = 0;
        if (t >= o) v = ssum[t - o];
        __syncthreads();
        if (t >= o) ssum[t] += v;
        __syncthreads();
    }
    int run = (t == 0) ? 0 : ssum[t - 1];
    for (int i = 0; i < chunk; i++) {
        int idx = base + i;
        if (idx < N) {
            g_off[idx] = run;
            g_pos[idx] = run;
            run += g_cnt[idx];
        }
    }
    if (t == 0) g_off[N] = E;
}

// K4: scatter edges into CSR slots; compute coef here; single packed 8B store.
__global__ void scatter_kernel(const int* __restrict__ ei,
                               const float* __restrict__ ew, int E) {
    int i = blockIdx.x * blockDim.x + threadIdx.x;
    if (i >= E) return;
    int s = __ldg(ei + i);
    int d = __ldg(ei + E + i);
    float coef = tanhf(g_al[s] + g_ar[d]) * __ldg(ew + i);
    int p = atomicAdd(&g_pos[d], 1);
    g_edge[p] = make_int2(s, __float_as_int(coef));
}

// K5: warp-per-dst gather, 4-deep edge pipeline, register accumulation,
// fused 0.1*node_0 + LayerNorm + ReLU epilogue. Single store per output row.
__global__ void agg_ln_kernel(const float* __restrict__ node,
                              const float* __restrict__ node0,
                              const float* __restrict__ w,
                              const float* __restrict__ b,
                              float* __restrict__ out, int N) {
    int warp = threadIdx.x >> 5, lane = threadIdx.x & 31;
    int n = blockIdx.x * 8 + warp;
    if (n >= N) return;

    int k0 = __ldg(&g_off[n]);
    int k1 = __ldg(&g_off[n + 1]);

    float4 a0 = make_float4(0.f, 0.f, 0.f, 0.f);
    float4 a1 = make_float4(0.f, 0.f, 0.f, 0.f);

    int e = k0;
    // 4 edges per iteration: 8 independent float4 loads front-batched (MLP~8)
    for (; e + 3 < k1; e += 4) {
        int2 e0 = __ldg(g_edge + e);
        int2 e1 = __ldg(g_edge + e + 1);
        int2 e2 = __ldg(g_edge + e + 2);
        int2 e3 = __ldg(g_edge + e + 3);
        const float4* r0 = (const float4*)(node + (size_t)e0.x * D);
        const float4* r1 = (const float4*)(node + (size_t)e1.x * D);
        const float4* r2 = (const float4*)(node + (size_t)e2.x * D);
        const float4* r3 = (const float4*)(node + (size_t)e3.x * D);
        float4 v0 = __ldg(r0 + lane), u0 = __ldg(r0 + lane + 32);
        float4 v1 = __ldg(r1 + lane), u1 = __ldg(r1 + lane + 32);
        float4 v2 = __ldg(r2 + lane), u2 = __ldg(r2 + lane + 32);
        float4 v3 = __ldg(r3 + lane), u3 = __ldg(r3 + lane + 32);
        float c0 = __int_as_float(e0.y);
        float c1 = __int_as_float(e1.y);
        float c2 = __int_as_float(e2.y);
        float c3 = __int_as_float(e3.y);
        a0.x += v0.x * c0; a0.y += v0.y * c0; a0.z += v0.z * c0; a0.w += v0.w * c0;
        a1.x += u0.x * c0; a1.y += u0.y * c0; a1.z += u0.z * c0; a1.w += u0.w * c0;
        a0.x += v1.x * c1; a0.y += v1.y * c1; a0.z += v1.z * c1; a0.w += v1.w * c1;
        a1.x += u1.x * c1; a1.y += u1.y * c1; a1.z += u1.z * c1; a1.w += u1.w * c1;
        a0.x += v2.x * c2; a0.y += v2.y * c2; a0.z += v2.z * c2; a0.w += v2.w * c2;
        a1.x += u2.x * c2; a1.y += u2.y * c2; a1.z += u2.z * c2; a1.w += u2.w * c2;
        a0.x += v3.x * c3; a0.y += v3.y * c3; a0.z += v3.z * c3; a0.w += v3.w * c3;
        a1.x += u3.x * c3; a1.y += u3.y * c3; a1.z += u3.z * c3; a1.w += u3.w * c3;
    }
    for (; e < k1; e++) {
        int2 e0 = __ldg(g_edge + e);
        float c0 = __int_as_float(e0.y);
        const float4* r0 = (const float4*)(node + (size_t)e0.x * D);
        float4 v0 = __ldg(r0 + lane), u0 = __ldg(r0 + lane + 32);
        a0.x += v0.x * c0; a0.y += v0.y * c0; a0.z += v0.z * c0; a0.w += v0.w * c0;
        a1.x += u0.x * c0; a1.y += u0.y * c0; a1.z += u0.z * c0; a1.w += u0.w * c0;
    }

    // + 0.1 * node_0
    const float4* row0 = (const float4*)(node0 + (size_t)n * D);
    float4 z0 = __ldg(row0 + lane), z1 = __ldg(row0 + lane + 32);
    a0.x += 0.1f * z0.x; a0.y += 0.1f * z0.y; a0.z += 0.1f * z0.z; a0.w += 0.1f * z0.w;
    a1.x += 0.1f * z1.x; a1.y += 0.1f * z1.y; a1.z += 0.1f * z1.z; a1.w += 0.1f * z1.w;

    // LayerNorm over D=256 + ReLU
    float sum = a0.x + a0.y + a0.z + a0.w + a1.x + a1.y + a1.z + a1.w;
    float sq  = a0.x * a0.x + a0.y * a0.y + a0.z * a0.z + a0.w * a0.w
              + a1.x * a1.x + a1.y * a1.y + a1.z * a1.z + a1.w * a1.w;
#pragma unroll
    for (int o = 16; o > 0; o >>= 1) {
        sum += __shfl_xor_sync(0xffffffffu, sum, o);
        sq  += __shfl_xor_sync(0xffffffffu, sq, o);
    }
    float mean = sum * (1.0f / D);
    float var  = sq * (1.0f / D) - mean * mean;
    float inv  = rsqrtf(var + 1e-5f);

    const float4* w4 = (const float4*)w;
    const float4* b4 = (const float4*)b;
    float4* orow = (float4*)(out + (size_t)n * D);
#pragma unroll
    for (int i = 0; i < 2; i++) {
        int idx = lane + 32 * i;
        float4 v = (i == 0) ? a0 : a1;
        float4 ww = __ldg(w4 + idx);
        float4 bb = __ldg(b4 + idx);
        float4 r;
        r.x = fmaxf((v.x - mean) * inv * ww.x + bb.x, 0.0f);
        r.y = fmaxf((v.y - mean) * inv * ww.y + bb.y, 0.0f);
        r.z = fmaxf((v.z - mean) * inv * ww.z + bb.z, 0.0f);
        r.w = fmaxf((v.w - mean) * inv * ww.w + bb.w, 0.0f);
        orow[idx] = r;
    }
}

extern "C" void kernel_launch(void* const* d_in, const int* in_sizes, int n_in,
                              void* d_out, int out_size) {
    const float* node  = (const float*)d_in[0];
    const float* node0 = (const float*)d_in[1];
    const int*   ei    = (const int*)d_in[2];
    const float* ew    = (const float*)d_in[3];
    // d_in[4] = batch_ptr (unused in node-mode LayerNorm)
    const float* att_l = (const float*)d_in[5];
    const float* att_r = (const float*)d_in[6];
    const float* lnw   = (const float*)d_in[7];
    const float* lnb   = (const float*)d_in[8];
    float* out = (float*)d_out;

    int N = in_sizes[0] / D;
    int E = in_sizes[3];

    node_pre_kernel<<<(N + 7) / 8, 256>>>(node, att_l, att_r, N);
    hist_kernel<<<((E >> 2) + 255) / 256, 256>>>(ei, E);
    scan_kernel<<<1, 1024>>>(N, E);
    scatter_kernel<<<(E + 255) / 256, 256>>>(ei, ew, E);
    agg_ln_kernel<<<(N + 7) / 8, 256>>>(node, node0, lnw, lnb, out, N);
}